// round 2
// baseline (speedup 1.0000x reference)
#include <cuda_runtime.h>

#define FULL 0xffffffffu
#define KWARPS 8
#define TPB (KWARPS * 32)

// smem scratch per warp (floats):
//  xks   [160]  neighbor features (rank-major, 5 per rank)
//  featS [136]  (128 argmax indices + rel(2) + vel(2), padded)
//  z1s   [64]
//  z2s   [128]
//  z3s   [64]
//  kS    [4]    + 4 pad
#define WSCR 560

__global__ __launch_bounds__(TPB) void controller_kernel(
    const float* __restrict__ states, const float* __restrict__ goals,
    const float* __restrict__ W1, const float* __restrict__ b1,
    const float* __restrict__ W2, const float* __restrict__ b2,
    const float* __restrict__ Wd1, const float* __restrict__ bd1,
    const float* __restrict__ Wd2, const float* __restrict__ bd2,
    const float* __restrict__ Wd3, const float* __restrict__ bd3,
    const float* __restrict__ Wd4, const float* __restrict__ bd4,
    float* __restrict__ out, int n)
{
    extern __shared__ char smem_raw[];
    float2* sxy = (float2*)smem_raw;              // n float2
    float*  W1s = (float*)(sxy + n);              // 320
    float*  b1s = W1s + 320;                      // 64
    float*  W2s = b1s + 64;                       // 8192
    float*  b2s = W2s + 8192;                     // 128
    float*  scratch = b2s + 128;                  // KWARPS * WSCR

    const int tid  = threadIdx.x;
    const int lane = tid & 31;
    const int warp = tid >> 5;

    const float4* st4 = (const float4*)states;

    // cooperative staging
    for (int j = tid; j < n; j += TPB) {
        float4 s = st4[j];
        sxy[j] = make_float2(s.x, s.y);
    }
    for (int j = tid; j < 320;  j += TPB) W1s[j] = W1[j];
    for (int j = tid; j < 64;   j += TPB) b1s[j] = b1[j];
    for (int j = tid; j < 8192; j += TPB) W2s[j] = W2[j];
    for (int j = tid; j < 128;  j += TPB) b2s[j] = b2[j];
    __syncthreads();

    const int i = blockIdx.x * KWARPS + warp;
    if (i >= n) return;

    float* wscr  = scratch + warp * WSCR;
    float* xks   = wscr;          // 160
    float* featS = wscr + 160;    // 136
    float* z1s   = wscr + 296;    // 64
    float* z2s   = wscr + 360;    // 128
    float* z3s   = wscr + 488;    // 64
    float* kS    = wscr + 552;    // 4

    const float4 si = st4[i];
    const float six = si.x, siy = si.y;

    // ---------------- Phase 1: top-32 nearest (key = (bits(d)<<32)|j) -------
    // R: one key per lane, sorted ascending across lanes. Insertion sort with
    // ballot early-reject: only keys beating the current 32nd enter.
    unsigned long long R = ~0ull;
    unsigned long long keyMax = ~0ull;

    for (int base = 0; base < n; base += 32) {
        const int j = base + lane;
        const float2 p = sxy[j];
        const float dx = six - p.x;
        const float dy = siy - p.y;
        // match reference rounding: (dx*dx + dy*dy) + 1e-4, then sqrt (no fma)
        const float d2 = __fadd_rn(__fadd_rn(__fmul_rn(dx, dx), __fmul_rn(dy, dy)), 1e-4f);
        const float d  = __fsqrt_rn(d2);
        const unsigned long long key =
            ((unsigned long long)__float_as_uint(d) << 32) | (unsigned)j;

        unsigned cm = __ballot_sync(FULL, key < keyMax);
        while (cm) {
            const int c = __ffs(cm) - 1;
            cm &= cm - 1;
            const unsigned long long k = __shfl_sync(FULL, key, c);
            if (k < keyMax) {   // uniform branch (keyMax uniform)
                const int pos = __popc(__ballot_sync(FULL, R < k));
                const unsigned long long up = __shfl_up_sync(FULL, R, 1);
                R = (lane < pos) ? R : (lane == pos ? k : up);
                keyMax = __shfl_sync(FULL, R, 31);
            }
        }
    }

    // ---------------- Phase 2: gather neighbor features ---------------------
    const int j = (int)(unsigned)(R & 0xffffffffull);   // lane = neighbor rank
    const float4 sj = st4[j];
    const float x0 = si.x - sj.x;
    const float x1 = si.y - sj.y;
    const float x2 = si.z - sj.z;
    const float x3 = si.w - sj.w;
    const float x4 = (j == i) ? 1.0f : 0.0f;
    const float dist = __fsqrt_rn(__fadd_rn(__fmul_rn(x0, x0), __fmul_rn(x1, x1)));
    const float msk  = (dist < 1.0f) ? 1.0f : 0.0f;   // mask indexed by rank == position

    xks[lane * 5 + 0] = x0;
    xks[lane * 5 + 1] = x1;
    xks[lane * 5 + 2] = x2;
    xks[lane * 5 + 3] = x3;
    xks[lane * 5 + 4] = x4;
    __syncwarp();

    // raw reshape [32,5] -> [5,32]: h[c][p] = flat[c*32+p]; lane = position p
    const float h0 = xks[  0 + lane];
    const float h1 = xks[ 32 + lane];
    const float h2 = xks[ 64 + lane];
    const float h3 = xks[ 96 + lane];
    const float h4 = xks[128 + lane];

    // ---------------- Phase 3a: conv1 5 -> 64 (relu) ------------------------
    float o1[64];
#pragma unroll
    for (int o = 0; o < 64; ++o) {
        const float* w = W1s + o * 5;
        float a = __fmul_rn(w[0], h0);
        a = fmaf(w[1], h1, a);
        a = fmaf(w[2], h2, a);
        a = fmaf(w[3], h3, a);
        a = fmaf(w[4], h4, a);
        a = __fadd_rn(a, b1s[o]);
        o1[o] = fmaxf(a, 0.0f);
    }

    // ---------------- Phase 3b: conv2 64 -> 128 + masked argmax -------------
    for (int q = 0; q < 128; ++q) {
        const float4* w = (const float4*)(W2s + q * 64);
        float a = 0.0f;
#pragma unroll
        for (int t = 0; t < 16; ++t) {
            const float4 w4 = w[t];
            a = fmaf(w4.x, o1[4 * t + 0], a);
            a = fmaf(w4.y, o1[4 * t + 1], a);
            a = fmaf(w4.z, o1[4 * t + 2], a);
            a = fmaf(w4.w, o1[4 * t + 3], a);
        }
        a = __fadd_rn(a, b2s[q]);
        a = fmaxf(a, 0.0f);
        const float v = __fmul_rn(a, msk);          // v >= 0
        const unsigned vb   = __float_as_uint(v);   // monotonic for v >= 0
        const unsigned vmax = __reduce_max_sync(FULL, vb);
        const int bp = __ffs(__ballot_sync(FULL, vb == vmax)) - 1;  // tie -> lowest p
        if (lane == 0) featS[q] = (float)bp;
    }

    // ---------------- Phase 4: MLP 132 -> 64 -> 128 -> 64 -> 4 --------------
    if (lane == 0) {
        const float2 g = ((const float2*)goals)[i];
        featS[128] = si.x - g.x;
        featS[129] = si.y - g.y;
        featS[130] = si.z;
        featS[131] = si.w;
    }
    __syncwarp();

    // layer 1: 132 -> 64, 2 neurons per lane
#pragma unroll
    for (int r = 0; r < 2; ++r) {
        const int nn = lane + 32 * r;
        const float4* w  = (const float4*)(Wd1 + nn * 132);
        const float4* f4 = (const float4*)featS;
        float a = 0.0f;
#pragma unroll
        for (int t = 0; t < 33; ++t) {
            const float4 wv = w[t];
            const float4 fv = f4[t];
            a = fmaf(wv.x, fv.x, a); a = fmaf(wv.y, fv.y, a);
            a = fmaf(wv.z, fv.z, a); a = fmaf(wv.w, fv.w, a);
        }
        a = __fadd_rn(a, bd1[nn]);
        z1s[nn] = fmaxf(a, 0.0f);
    }
    __syncwarp();

    // layer 2: 64 -> 128, 4 neurons per lane
#pragma unroll
    for (int r = 0; r < 4; ++r) {
        const int nn = lane + 32 * r;
        const float4* w  = (const float4*)(Wd2 + nn * 64);
        const float4* f4 = (const float4*)z1s;
        float a = 0.0f;
#pragma unroll
        for (int t = 0; t < 16; ++t) {
            const float4 wv = w[t];
            const float4 fv = f4[t];
            a = fmaf(wv.x, fv.x, a); a = fmaf(wv.y, fv.y, a);
            a = fmaf(wv.z, fv.z, a); a = fmaf(wv.w, fv.w, a);
        }
        a = __fadd_rn(a, bd2[nn]);
        z2s[nn] = fmaxf(a, 0.0f);
    }
    __syncwarp();

    // layer 3: 128 -> 64, 2 neurons per lane
#pragma unroll
    for (int r = 0; r < 2; ++r) {
        const int nn = lane + 32 * r;
        const float4* w  = (const float4*)(Wd3 + nn * 128);
        const float4* f4 = (const float4*)z2s;
        float a = 0.0f;
#pragma unroll
        for (int t = 0; t < 32; ++t) {
            const float4 wv = w[t];
            const float4 fv = f4[t];
            a = fmaf(wv.x, fv.x, a); a = fmaf(wv.y, fv.y, a);
            a = fmaf(wv.z, fv.z, a); a = fmaf(wv.w, fv.w, a);
        }
        a = __fadd_rn(a, bd3[nn]);
        z3s[nn] = fmaxf(a, 0.0f);
    }
    __syncwarp();

    // layer 4: 64 -> 4, gains
    if (lane < 4) {
        const float4* w  = (const float4*)(Wd4 + lane * 64);
        const float4* f4 = (const float4*)z3s;
        float a = 0.0f;
#pragma unroll
        for (int t = 0; t < 16; ++t) {
            const float4 wv = w[t];
            const float4 fv = f4[t];
            a = fmaf(wv.x, fv.x, a); a = fmaf(wv.y, fv.y, a);
            a = fmaf(wv.z, fv.z, a); a = fmaf(wv.w, fv.w, a);
        }
        a = __fadd_rn(a, bd4[lane]);
        kS[lane] = 2.0f / (1.0f + expf(-a)) + 0.2f;
    }
    __syncwarp();

    if (lane == 0) {
        const float k0 = kS[0], k1 = kS[1], k2 = kS[2], k3 = kS[3];
        const float relx = featS[128], rely = featS[129];
        const float vx = si.z, vy = si.w;
        const float ax = -__fadd_rn(__fmul_rn(k0, relx), __fmul_rn(k1, vx));
        const float ay = -__fadd_rn(__fmul_rn(k2, rely), __fmul_rn(k3, vy));
        ((float2*)out)[i] = make_float2(ax, ay);
    }
}

extern "C" void kernel_launch(void* const* d_in, const int* in_sizes, int n_in,
                              void* d_out, int out_size)
{
    const float* states = (const float*)d_in[0];
    const float* goals  = (const float*)d_in[1];
    const float* W1  = (const float*)d_in[2];
    const float* b1  = (const float*)d_in[3];
    const float* W2  = (const float*)d_in[4];
    const float* b2  = (const float*)d_in[5];
    const float* Wd1 = (const float*)d_in[6];
    const float* bd1 = (const float*)d_in[7];
    const float* Wd2 = (const float*)d_in[8];
    const float* bd2 = (const float*)d_in[9];
    const float* Wd3 = (const float*)d_in[10];
    const float* bd3 = (const float*)d_in[11];
    const float* Wd4 = (const float*)d_in[12];
    const float* bd4 = (const float*)d_in[13];

    const int n = in_sizes[0] / 4;
    const int blocks = (n + KWARPS - 1) / KWARPS;
    const size_t smem = (size_t)n * sizeof(float2)
                      + (320 + 64 + 8192 + 128) * sizeof(float)
                      + (size_t)KWARPS * WSCR * sizeof(float);

    cudaFuncSetAttribute(controller_kernel,
                         cudaFuncAttributeMaxDynamicSharedMemorySize, (int)smem);

    controller_kernel<<<blocks, TPB, smem>>>(
        states, goals, W1, b1, W2, b2,
        Wd1, bd1, Wd2, bd2, Wd3, bd3, Wd4, bd4,
        (float*)d_out, n);
}